// round 9
// baseline (speedup 1.0000x reference)
#include <cuda_runtime.h>
#include <cuda_bf16.h>
#include <math.h>
#include <float.h>

// Problem constants
#define H_     512
#define W_     512
#define HW     (H_ * W_)          // 262144
#define NORG   10
#define SS_    32
#define CH_SHP   1                // channels 1..1024
#define CH_SIZE  1025             // channels 1025,1026
#define CH_HEAT  1027             // channels 1027..1036

// Output layout (flattened tuple, fp32):
//   [0, 2*HW)              size    (2,512,512)
//   [2*HW, 2*HW+20)        centers (10,2) as [px, py]
//   [2*HW+20, ...)         final   (10,512,512)
#define OFF_CENTERS (2 * HW)
#define OFF_FINAL   (2 * HW + 2 * NORG)   // 524308; %4==0 -> float4-aligned

#define NSEG 64                   // segments per org
#define SEG_LEN (HW / NSEG)       // 4096 elements
#define NBLOCKS (NSEG * NORG)     // 640

#define BOX_BLOCKS 64             // blocks per org in box kernel

__device__ float g_pval[NORG * NSEG];
__device__ int   g_pidx[NORG * NSEG];
__device__ int   g_r0[NORG], g_c0[NORG], g_sh[NORG], g_sw[NORG];
__device__ __align__(16) float g_shape[NORG * SS_ * SS_];   // 10 x 32 x 32
__device__ unsigned int g_done;   // zero-init; self-resetting each replay

// ---------------------------------------------------------------------------
// Kernel 1: per-(org,segment) argmax scan (float4, MLP=4)
//         + streaming zero-fill of the `final` output region
//         + size-channel transform (abs(trunc))
//         + fused last-block reduce / params / centers / shape gather.
// First-occurrence tie-break preserved throughout.
// ---------------------------------------------------------------------------
__global__ void __launch_bounds__(256)
argmax_fused_kernel(const float* __restrict__ feat, float* __restrict__ out) {
    const int o   = blockIdx.y;
    const int seg = blockIdx.x;
    const int tid = threadIdx.x;
    const int bl  = o * NSEG + seg;          // 0..639

    // ---- heat scan: this block's 4096-element segment ----
    const float4* h4 = (const float4*)(feat + (size_t)(CH_HEAT + o) * HW
                                       + (size_t)seg * SEG_LEN);
    float best = -FLT_MAX;
    int   bidx = 0x7FFFFFFF;
    #pragma unroll
    for (int j = 0; j < 4; j++) {
        const int q = tid + j * 256;         // ascending per thread
        float4 v = h4[q];
        const int base = seg * SEG_LEN + q * 4;
        if (v.x > best) { best = v.x; bidx = base;     }
        if (v.y > best) { best = v.y; bidx = base + 1; }
        if (v.z > best) { best = v.z; bidx = base + 2; }
        if (v.w > best) { best = v.w; bidx = base + 3; }
    }

    // ---- independent streaming work (overlaps the scan's latency) ----
    // zero-fill `final`: exactly 1024 float4 per block (640*1024 = 10*HW/4)
    {
        float4 z; z.x = 0.f; z.y = 0.f; z.z = 0.f; z.w = 0.f;
        float4* foz = (float4*)(out + OFF_FINAL) + (size_t)bl * 1024;
        #pragma unroll
        for (int i = 0; i < 4; i++)
            foz[tid + i * 256] = z;
    }
    // size channels: 2*HW floats = 131072 float4 over 163840 threads
    {
        const int s = bl * 256 + tid;
        if (s < (2 * HW) / 4) {
            float4 v = ((const float4*)(feat + (size_t)CH_SIZE * HW))[s];
            float4 w;
            w.x = fabsf((float)(int)v.x);
            w.y = fabsf((float)(int)v.y);
            w.z = fabsf((float)(int)v.z);
            w.w = fabsf((float)(int)v.w);
            ((float4*)out)[s] = w;
        }
    }

    // ---- block reduce of argmax ----
    __shared__ float sv[256];
    __shared__ int   si[256];
    sv[tid] = best; si[tid] = bidx;
    __syncthreads();
    for (int s = 128; s > 0; s >>= 1) {
        if (tid < s) {
            float v2 = sv[tid + s];
            int   i2 = si[tid + s];
            if (v2 > sv[tid] || (v2 == sv[tid] && i2 < si[tid])) {
                sv[tid] = v2; si[tid] = i2;
            }
        }
        __syncthreads();
    }
    if (tid == 0) {
        g_pval[o * NSEG + seg] = sv[0];
        g_pidx[o * NSEG + seg] = si[0];
    }

    // ---- last-arriving block finishes ----
    __shared__ int s_last;
    __threadfence();
    if (tid == 0) {
        unsigned int prev = atomicAdd(&g_done, 1u);
        s_last = (prev == NBLOCKS - 1);
        if (s_last) g_done = 0;              // reset for next graph replay
    }
    __syncthreads();
    if (!s_last) return;
    __threadfence();

    __shared__ int s_idx[NORG];
    const int wid  = tid >> 5;
    const int lane = tid & 31;

    for (int oo = wid; oo < NORG; oo += 8) {
        float v1 = g_pval[oo * NSEG + lane];
        int   i1 = g_pidx[oo * NSEG + lane];
        float v2 = g_pval[oo * NSEG + lane + 32];
        int   i2 = g_pidx[oo * NSEG + lane + 32];
        if (v2 > v1 || (v2 == v1 && i2 < i1)) { v1 = v2; i1 = i2; }
        #pragma unroll
        for (int s = 16; s > 0; s >>= 1) {
            float vo = __shfl_down_sync(0xFFFFFFFFu, v1, s);
            int   io = __shfl_down_sync(0xFFFFFFFFu, i1, s);
            if (vo > v1 || (vo == v1 && io < i1)) { v1 = vo; i1 = io; }
        }
        if (lane == 0) s_idx[oo] = i1;
    }
    __syncthreads();

    if (tid < NORG) {
        const int bi = s_idx[tid];
        const int py = bi / W_;
        const int px = bi % W_;

        int s0 = abs((int)feat[(size_t)CH_SIZE * HW + bi]);
        int s1 = abs((int)feat[(size_t)(CH_SIZE + 1) * HW + bi]);
        int sh = s0 > 1 ? s0 : 1;
        int sw = s1 > 1 ? s1 : 1;
        g_sh[tid] = sh;
        g_sw[tid] = sw;
        g_r0[tid] = py - sh / 2;
        g_c0[tid] = px - sw / 2;

        out[OFF_CENTERS + tid * 2 + 0] = (float)px;
        out[OFF_CENTERS + tid * 2 + 1] = (float)py;
    }
    __syncthreads();

    // shape gather: 10240 independent scattered loads across 256 threads
    for (int i = tid; i < NORG * SS_ * SS_; i += 256) {
        const int oo = i >> 10;
        const int c  = i & 1023;
        g_shape[i] = feat[(size_t)(CH_SHP + c) * HW + s_idx[oo]];
    }
}

// ---------------------------------------------------------------------------
// Kernel 2: box-interior-only compute. grid = (BOX_BLOCKS, NORG).
// `final` is already zeroed; only overwrite clipped box pixels.
// ---------------------------------------------------------------------------
__global__ void __launch_bounds__(256)
box_kernel(const float* __restrict__ feat, float* __restrict__ out) {
    const int o   = blockIdx.y;
    const int tid = threadIdx.x;

    __shared__ __align__(16) float s_shape[SS_ * SS_];   // 4 KB
    __shared__ int   s_r0, s_c0, s_rlo, s_clo, s_nr, s_nc;
    __shared__ float s_ih, s_iw;

    ((float4*)s_shape)[tid] = ((const float4*)(g_shape + o * (SS_ * SS_)))[tid];
    if (tid == 0) {
        int r0 = g_r0[o], c0 = g_c0[o], sh = g_sh[o], sw = g_sw[o];
        s_r0 = r0; s_c0 = c0;
        s_ih = (float)SS_ / (float)sh;
        s_iw = (float)SS_ / (float)sw;
        int rlo = r0 > 0 ? r0 : 0;
        int rhi = r0 + sh < H_ ? r0 + sh : H_;
        int clo = c0 > 0 ? c0 : 0;
        int chi = c0 + sw < W_ ? c0 + sw : W_;
        s_rlo = rlo; s_clo = clo;
        s_nr = rhi - rlo; s_nc = chi - clo;
    }
    __syncthreads();

    const int nr = s_nr, nc = s_nc;
    if (nr <= 0 || nc <= 0) return;
    const int total = nr * nc;
    const int r0o = s_r0, c0o = s_c0, rlo = s_rlo, clo = s_clo;
    const float iho = s_ih, iwo = s_iw;
    float* fo = out + OFF_FINAL + (size_t)o * HW;

    for (int idx = blockIdx.x * 256 + tid; idx < total; idx += BOX_BLOCKS * 256) {
        const int rr = idx / nc;
        const int cc = idx - rr * nc;
        const int r = rlo + rr;
        const int c = clo + cc;
        const int p = r * W_ + c;

        float sal = 1.0f / (1.0f + expf(-feat[p]));

        float sy = ((float)(r - r0o) + 0.5f) * iho - 0.5f;
        float sx = ((float)(c - c0o) + 0.5f) * iwo - 0.5f;
        sy = fminf(fmaxf(sy, 0.0f), (float)(SS_ - 1));
        sx = fminf(fmaxf(sx, 0.0f), (float)(SS_ - 1));
        int y0 = (int)floorf(sy);
        int x0 = (int)floorf(sx);
        int y1 = min(y0 + 1, SS_ - 1);
        int x1 = min(x0 + 1, SS_ - 1);
        float wy = sy - (float)y0;
        float wx = sx - (float)x0;
        float v00 = s_shape[y0 * SS_ + x0];
        float v01 = s_shape[y0 * SS_ + x1];
        float v10 = s_shape[y1 * SS_ + x0];
        float v11 = s_shape[y1 * SS_ + x1];
        float loc = (1.0f - wy) * ((1.0f - wx) * v00 + wx * v01)
                  +          wy * ((1.0f - wx) * v10 + wx * v11);

        fo[p] = sal / (1.0f + expf(-loc));
    }
}

// ---------------------------------------------------------------------------
extern "C" void kernel_launch(void* const* d_in, const int* in_sizes, int n_in,
                              void* d_out, int out_size) {
    const float* feat = (const float*)d_in[0];
    float* out = (float*)d_out;

    dim3 g1(NSEG, NORG);
    argmax_fused_kernel<<<g1, 256>>>(feat, out);
    dim3 g2(BOX_BLOCKS, NORG);
    box_kernel<<<g2, 256>>>(feat, out);
}